// round 1
// baseline (speedup 1.0000x reference)
#include <cuda_runtime.h>
#include <math.h>

#define VOCAB 32000
#define EMB   300
#define NFLT  100
#define HID   256
#define NOUT  32
#define BB    32
#define TT    64
#define LL    48
#define NCOL  1200          // concat conv projection columns (3+4+5)*100
#define BT    (BB*TT)

// ---------------- device scratch (no allocations allowed) ----------------
__device__ float g_P[VOCAB * NCOL];        // 153.6 MB vocab projection
__device__ float g_Wcat[EMB * NCOL];       // repacked conv weights [e][c]
__device__ float g_rin[BT * 300];          // conv features [b*T+t][300]
__device__ float g_XG[2 * TT * 1024 * BB]; // [dir][t][gate*256+j][b]
__device__ float g_HS[2 * TT * HID * BB];  // [dir][t][j][b]
__device__ float g_Hbuf[2 * 2 * HID * BB]; // [buf][dir][j*32+b]
__device__ int   g_bar[TT];                // per-step barrier counters

__device__ __forceinline__ float sigf(float x) { return 1.0f / (1.0f + expf(-x)); }

// ---------------- init: zero h ping-pong + barriers ----------------
__global__ void init_kernel() {
    int idx = blockIdx.x * blockDim.x + threadIdx.x;
    int n = 2 * 2 * HID * BB;
    for (int i = idx; i < n; i += gridDim.x * blockDim.x) g_Hbuf[i] = 0.0f;
    if (idx < TT) g_bar[idx] = 0;
}

// ---------------- repack conv weights into Wcat[e][c], c = cbase + k*100 + nf ----------------
__global__ void repack_kernel(const float* __restrict__ w3,
                              const float* __restrict__ w4,
                              const float* __restrict__ w5) {
    int idx = blockIdx.x * blockDim.x + threadIdx.x;
    if (idx >= EMB * NCOL) return;
    int e  = idx / NCOL;
    int cc = idx % NCOL;
    float v;
    if (cc < 300)       { int k = cc / 100,        nf = cc % 100;        v = w3[(nf * EMB + e) * 3 + k]; }
    else if (cc < 700)  { int c2 = cc - 300; int k = c2 / 100, nf = c2 % 100; v = w4[(nf * EMB + e) * 4 + k]; }
    else                { int c2 = cc - 700; int k = c2 / 100, nf = c2 % 100; v = w5[(nf * EMB + e) * 5 + k]; }
    g_Wcat[idx] = v;
}

// ---------------- SGEMM: P[32000][1200] = emb[32000][300] @ Wcat[300][1200] ----------------
// 128x64 block tile, 8x4 per thread, 256 threads, BK=16.
__global__ void sgemm_P_kernel(const float* __restrict__ A) {
    const int M = VOCAB, N = NCOL, K = EMB;
    __shared__ float sA[16][132];
    __shared__ float sB[16][68];
    int bm = blockIdx.y * 128;
    int bn = blockIdx.x * 64;
    int tid = threadIdx.x;
    int tx = tid & 15, ty = tid >> 4;
    float acc[8][4] = {};
    for (int kk = 0; kk < K; kk += 16) {
        int ak = tid & 15, am = tid >> 4;
        int gk = kk + ak;
#pragma unroll
        for (int i = 0; i < 8; i++) {
            int m = am + i * 16;
            sA[ak][m] = (gk < K) ? __ldg(&A[(size_t)(bm + m) * K + gk]) : 0.0f;
        }
        int bnl = tid & 63, bk0 = tid >> 6;
#pragma unroll
        for (int i = 0; i < 4; i++) {
            int k = bk0 + i * 4;
            int gkb = kk + k;
            int gn  = bn + bnl;
            sB[k][bnl] = (gkb < K && gn < N) ? __ldg(&g_Wcat[gkb * N + gn]) : 0.0f;
        }
        __syncthreads();
#pragma unroll
        for (int k = 0; k < 16; k++) {
            float4 a0 = *(const float4*)&sA[k][ty * 8];
            float4 a1 = *(const float4*)&sA[k][ty * 8 + 4];
            float4 b0 = *(const float4*)&sB[k][tx * 4];
            float ra[8] = {a0.x, a0.y, a0.z, a0.w, a1.x, a1.y, a1.z, a1.w};
            float rb[4] = {b0.x, b0.y, b0.z, b0.w};
#pragma unroll
            for (int i = 0; i < 8; i++)
#pragma unroll
                for (int j = 0; j < 4; j++) acc[i][j] += ra[i] * rb[j];
        }
        __syncthreads();
    }
#pragma unroll
    for (int i = 0; i < 8; i++) {
        int gm = bm + ty * 8 + i;
#pragma unroll
        for (int j = 0; j < 4; j++) {
            int gn = bn + tx * 4 + j;
            if (gn < N) g_P[(size_t)gm * N + gn] = acc[i][j];
        }
    }
    (void)M;
}

// ---------------- conv gather + max-pool + bias + relu ----------------
__global__ void conv_gather_kernel(const int* __restrict__ dia,
                                   const float* __restrict__ b3,
                                   const float* __restrict__ b4,
                                   const float* __restrict__ b5) {
    int bt = blockIdx.x;
    __shared__ int tok[LL];
    int tid = threadIdx.x;
    if (tid < LL) tok[tid] = dia[bt * LL + tid] * NCOL;
    __syncthreads();
    if (tid >= NFLT) return;
    int nf = tid;
    const float* P = g_P;

    float m3 = -1e30f;
    for (int p = 0; p < 46; p++) {
        float s = __ldg(&P[(size_t)tok[p] + nf]) +
                  __ldg(&P[(size_t)tok[p + 1] + 100 + nf]) +
                  __ldg(&P[(size_t)tok[p + 2] + 200 + nf]);
        m3 = fmaxf(m3, s);
    }
    g_rin[bt * 300 + nf] = fmaxf(m3 + b3[nf], 0.0f);

    float m4 = -1e30f;
    for (int p = 0; p < 45; p++) {
        float s = __ldg(&P[(size_t)tok[p] + 300 + nf]) +
                  __ldg(&P[(size_t)tok[p + 1] + 400 + nf]) +
                  __ldg(&P[(size_t)tok[p + 2] + 500 + nf]) +
                  __ldg(&P[(size_t)tok[p + 3] + 600 + nf]);
        m4 = fmaxf(m4, s);
    }
    g_rin[bt * 300 + 100 + nf] = fmaxf(m4 + b4[nf], 0.0f);

    float m5 = -1e30f;
    for (int p = 0; p < 44; p++) {
        float s = __ldg(&P[(size_t)tok[p] + 700 + nf]) +
                  __ldg(&P[(size_t)tok[p + 1] + 800 + nf]) +
                  __ldg(&P[(size_t)tok[p + 2] + 900 + nf]) +
                  __ldg(&P[(size_t)tok[p + 3] + 1000 + nf]) +
                  __ldg(&P[(size_t)tok[p + 4] + 1100 + nf]);
        m5 = fmaxf(m5, s);
    }
    g_rin[bt * 300 + 200 + nf] = fmaxf(m5 + b5[nf], 0.0f);
}

// ---------------- xg GEMM: XG[dir][t][g][b] = r_in @ w_ih^T + (b_ih+b_hh) ----------------
__global__ void xg_gemm_kernel(const float* __restrict__ wih_f, const float* __restrict__ wih_r,
                               const float* __restrict__ bih_f, const float* __restrict__ bhh_f,
                               const float* __restrict__ bih_r, const float* __restrict__ bhh_r) {
    const int K = 300;
    __shared__ float sA[16][132];
    __shared__ float sB[16][68];
    int dir = blockIdx.z;
    const float* W  = dir ? wih_r : wih_f;
    const float* bi = dir ? bih_r : bih_f;
    const float* bh = dir ? bhh_r : bhh_f;
    int bm = blockIdx.y * 128;   // m = t*32 + b
    int bn = blockIdx.x * 64;    // gate row g
    int tid = threadIdx.x;
    int tx = tid & 15, ty = tid >> 4;
    float acc[8][4] = {};
    for (int kk = 0; kk < K; kk += 16) {
        int ak = tid & 15, am = tid >> 4;
        int gk = kk + ak;
#pragma unroll
        for (int i = 0; i < 8; i++) {
            int m  = am + i * 16;
            int gm = bm + m;
            int t  = gm >> 5, bb = gm & 31;
            int st = dir ? (63 - t) : t;
            sA[ak][m] = (gk < K) ? __ldg(&g_rin[(bb * 64 + st) * 300 + gk]) : 0.0f;
        }
        int wk = tid & 15, wn = tid >> 4;
#pragma unroll
        for (int i = 0; i < 4; i++) {
            int n   = wn + i * 16;
            int gkb = kk + wk;
            sB[wk][n] = (gkb < K) ? __ldg(&W[(bn + n) * 300 + gkb]) : 0.0f;
        }
        __syncthreads();
#pragma unroll
        for (int k = 0; k < 16; k++) {
            float4 a0 = *(const float4*)&sA[k][ty * 8];
            float4 a1 = *(const float4*)&sA[k][ty * 8 + 4];
            float4 b0 = *(const float4*)&sB[k][tx * 4];
            float ra[8] = {a0.x, a0.y, a0.z, a0.w, a1.x, a1.y, a1.z, a1.w};
            float rb[4] = {b0.x, b0.y, b0.z, b0.w};
#pragma unroll
            for (int i = 0; i < 8; i++)
#pragma unroll
                for (int j = 0; j < 4; j++) acc[i][j] += ra[i] * rb[j];
        }
        __syncthreads();
    }
#pragma unroll
    for (int i = 0; i < 8; i++) {
        int gm = bm + ty * 8 + i;
        int t = gm >> 5, bb = gm & 31;
#pragma unroll
        for (int j = 0; j < 4; j++) {
            int g = bn + tx * 4 + j;
            g_XG[(((size_t)dir * 64 + t) * 1024 + g) * 32 + bb] =
                acc[i][j] + __ldg(&bi[g]) + __ldg(&bh[g]);
        }
    }
}

// ---------------- persistent BiLSTM: 64 CTAs (2 dirs x 32 hidden slices of 8) ----------------
__global__ void lstm_kernel(const float* __restrict__ whh_f, const float* __restrict__ whh_r) {
    extern __shared__ float sm[];
    float* sW = sm;                 // [8 jj][4 gate][256] = 8192 floats
    float* sH = sm + 8192;          // [32 b][260 pad]     = 8320 floats
    int cta = blockIdx.x;
    int dir = cta >> 5;
    int j0  = (cta & 31) * 8;
    int tid = threadIdx.x;
    int jj  = tid >> 5;
    int b   = tid & 31;
    const float* whh = dir ? whh_r : whh_f;

    for (int i = tid; i < 8192; i += 256) {
        int k = i & 255;
        int r = i >> 8;            // 0..31
        int gate = r & 3, jjj = r >> 2;
        sW[(jjj * 4 + gate) * 256 + k] = __ldg(&whh[(gate * 256 + j0 + jjj) * 256 + k]);
    }

    int j = j0 + jj;
    const float4* w0 = (const float4*)(sW + (jj * 4 + 0) * 256);
    const float4* w1 = (const float4*)(sW + (jj * 4 + 1) * 256);
    const float4* w2 = (const float4*)(sW + (jj * 4 + 2) * 256);
    const float4* w3 = (const float4*)(sW + (jj * 4 + 3) * 256);
    float c = 0.0f;
    __syncthreads();

    for (int s = 0; s < 64; s++) {
        int rb = s & 1;
        const float* hprev = g_Hbuf + (rb * 2 + dir) * (HID * BB);
        for (int i = tid; i < HID * BB; i += 256) {
            int jx = i >> 5, bx = i & 31;
            sH[bx * 260 + jx] = __ldcg(&hprev[i]);
        }
        __syncthreads();

        size_t xbase = (((size_t)dir * 64 + s) * 1024) * 32;
        float ai = __ldg(&g_XG[xbase + (size_t)(0   + j) * 32 + b]);
        float af = __ldg(&g_XG[xbase + (size_t)(256 + j) * 32 + b]);
        float ag = __ldg(&g_XG[xbase + (size_t)(512 + j) * 32 + b]);
        float ao = __ldg(&g_XG[xbase + (size_t)(768 + j) * 32 + b]);

        const float4* h4 = (const float4*)(sH + b * 260);
#pragma unroll 8
        for (int k = 0; k < 64; k++) {
            float4 h = h4[k];
            float4 x;
            x = w0[k]; ai += h.x * x.x + h.y * x.y + h.z * x.z + h.w * x.w;
            x = w1[k]; af += h.x * x.x + h.y * x.y + h.z * x.z + h.w * x.w;
            x = w2[k]; ag += h.x * x.x + h.y * x.y + h.z * x.z + h.w * x.w;
            x = w3[k]; ao += h.x * x.x + h.y * x.y + h.z * x.z + h.w * x.w;
        }

        float iv = sigf(ai), fv = sigf(af), gv = tanhf(ag), ov = sigf(ao);
        c = fv * c + iv * gv;
        float h = ov * tanhf(c);

        int wb = rb ^ 1;
        __stcg(&g_Hbuf[(wb * 2 + dir) * (HID * BB) + j * 32 + b], h);
        int tout = dir ? (63 - s) : s;
        g_HS[(((size_t)dir * 64 + tout) * HID + j) * 32 + b] = h;

        __threadfence();
        __syncthreads();
        if (tid == 0) {
            atomicAdd(&g_bar[s], 1);
            volatile int* bp = (volatile int*)&g_bar[s];
            while (*bp < 64) { __nanosleep(32); }
        }
        __syncthreads();
    }
}

// ---------------- head: out[b][t][o] = sigmoid([hf;hr] . head_w[o] + head_b[o]) ----------------
__global__ void head_kernel(const float* __restrict__ hw, const float* __restrict__ hb,
                            float* __restrict__ out) {
    int t = blockIdx.x;
    int tid = threadIdx.x;
    int b  = tid & 31;
    int og = tid >> 5;             // 8 groups of 4 outputs
    const float* hf = g_HS + (size_t)(t * HID) * 32;
    const float* hr = g_HS + (size_t)((64 + t) * HID) * 32;
    float a0 = 0.f, a1 = 0.f, a2 = 0.f, a3 = 0.f;
    int o = og * 4;
    for (int h = 0; h < HID; h++) {
        float vf = __ldg(&hf[h * 32 + b]);
        float vr = __ldg(&hr[h * 32 + b]);
        a0 += vf * __ldg(&hw[(o + 0) * 512 + h]) + vr * __ldg(&hw[(o + 0) * 512 + 256 + h]);
        a1 += vf * __ldg(&hw[(o + 1) * 512 + h]) + vr * __ldg(&hw[(o + 1) * 512 + 256 + h]);
        a2 += vf * __ldg(&hw[(o + 2) * 512 + h]) + vr * __ldg(&hw[(o + 2) * 512 + 256 + h]);
        a3 += vf * __ldg(&hw[(o + 3) * 512 + h]) + vr * __ldg(&hw[(o + 3) * 512 + 256 + h]);
    }
    size_t base = ((size_t)b * 64 + t) * 32 + o;
    out[base + 0] = sigf(a0 + __ldg(&hb[o + 0]));
    out[base + 1] = sigf(a1 + __ldg(&hb[o + 1]));
    out[base + 2] = sigf(a2 + __ldg(&hb[o + 2]));
    out[base + 3] = sigf(a3 + __ldg(&hb[o + 3]));
}

// ---------------- launch ----------------
extern "C" void kernel_launch(void* const* d_in, const int* in_sizes, int n_in,
                              void* d_out, int out_size) {
    const int*   dialogue = (const int*)d_in[0];
    const float* emb   = (const float*)d_in[1];
    const float* w3    = (const float*)d_in[2];
    const float* b3    = (const float*)d_in[3];
    const float* w4    = (const float*)d_in[4];
    const float* b4    = (const float*)d_in[5];
    const float* w5    = (const float*)d_in[6];
    const float* b5    = (const float*)d_in[7];
    const float* wih_f = (const float*)d_in[8];
    const float* whh_f = (const float*)d_in[9];
    const float* bih_f = (const float*)d_in[10];
    const float* bhh_f = (const float*)d_in[11];
    const float* wih_r = (const float*)d_in[12];
    const float* whh_r = (const float*)d_in[13];
    const float* bih_r = (const float*)d_in[14];
    const float* bhh_r = (const float*)d_in[15];
    const float* hw    = (const float*)d_in[16];
    const float* hb    = (const float*)d_in[17];
    float* out = (float*)d_out;

    cudaFuncSetAttribute(lstm_kernel, cudaFuncAttributeMaxDynamicSharedMemorySize,
                         (8192 + 32 * 260) * (int)sizeof(float));

    init_kernel<<<64, 256>>>();
    repack_kernel<<<(EMB * NCOL + 255) / 256, 256>>>(w3, w4, w5);

    dim3 gP((NCOL + 63) / 64, VOCAB / 128);
    sgemm_P_kernel<<<gP, 256>>>(emb);

    conv_gather_kernel<<<BT, 128>>>(dialogue, b3, b4, b5);

    dim3 gX(16, 16, 2);
    xg_gemm_kernel<<<gX, 256>>>(wih_f, wih_r, bih_f, bhh_f, bih_r, bhh_r);

    lstm_kernel<<<64, 256, (8192 + 32 * 260) * sizeof(float)>>>(whh_f, whh_r);

    head_kernel<<<TT, 256>>>(hw, hb, out);
}

// round 3
// speedup vs baseline: 1.4232x; 1.4232x over previous
#include <cuda_runtime.h>
#include <cuda_bf16.h>
#include <math.h>
#include <stdint.h>

#define VOCAB 32000
#define EMB   300
#define NFLT  100
#define HID   256
#define BB    32
#define TT    64
#define LL    48
#define NCOL  1200
#define BT    (BB*TT)

#define KP    320            // padded K per product block
#define KTOT  960            // 3 product blocks
#define NPAD  1280
#define MTILES 250
#define NTILES 10

// ---------------- device scratch ----------------
__device__ __align__(16) float g_P[(size_t)VOCAB * NCOL];          // 153.6 MB
__device__ __align__(16) __nv_bfloat16 g_A2[(size_t)VOCAB * KTOT]; // 61.4 MB
__device__ __align__(16) __nv_bfloat16 g_B2[(size_t)NPAD * KTOT];  // 2.4 MB
__device__ float g_rin[BT * 300];
__device__ float g_XG[2 * TT * 1024 * BB];
__device__ float g_HS[2 * TT * HID * BB];
__device__ float g_Hbuf[2 * 2 * HID * BB];
__device__ int   g_bar[TT];

__device__ __forceinline__ float sigf(float x) { return 1.0f / (1.0f + expf(-x)); }

__device__ __forceinline__ uint32_t smem_u32(const void* p) {
    uint32_t a;
    asm("{ .reg .u64 t; cvta.to.shared.u64 t, %1; cvt.u32.u64 %0, t; }" : "=r"(a) : "l"(p));
    return a;
}
#define CP_ASYNC16(d, s) asm volatile("cp.async.cg.shared.global [%0], [%1], 16;" :: "r"(d), "l"(s))
#define CP_COMMIT()      asm volatile("cp.async.commit_group;" ::: "memory")
#define CP_WAIT(n)       asm volatile("cp.async.wait_group %0;" :: "n"(n) : "memory")
#define LDMX4(r0, r1, r2, r3, addr) \
    asm volatile("ldmatrix.sync.aligned.m8n8.x4.shared.b16 {%0,%1,%2,%3}, [%4];" \
                 : "=r"(r0), "=r"(r1), "=r"(r2), "=r"(r3) : "r"(addr))
#define MMA16816(c, a, b) \
    asm volatile("mma.sync.aligned.m16n8k16.row.col.f32.bf16.bf16.f32 " \
                 "{%0,%1,%2,%3}, {%4,%5,%6,%7}, {%8,%9}, {%0,%1,%2,%3};" \
                 : "+f"((c)[0]), "+f"((c)[1]), "+f"((c)[2]), "+f"((c)[3]) \
                 : "r"((a)[0]), "r"((a)[1]), "r"((a)[2]), "r"((a)[3]), "r"((b)[0]), "r"((b)[1]))

// ---------------- init ----------------
__global__ void init_kernel() {
    int idx = blockIdx.x * blockDim.x + threadIdx.x;
    int n = 2 * 2 * HID * BB;
    for (int i = idx; i < n; i += gridDim.x * blockDim.x) g_Hbuf[i] = 0.0f;
    if (idx < TT) g_bar[idx] = 0;
}

// ---------------- build A2 = [Ahi | Ahi | Alo] bf16 row-major [m][960] ----------------
__global__ void convA_kernel(const float* __restrict__ emb) {
    int idx = blockIdx.x * blockDim.x + threadIdx.x;
    if (idx >= VOCAB * 160) return;
    int m  = idx / 160;
    int k2 = idx % 160;
    int k  = k2 * 2;
    float v0 = (k     < EMB) ? __ldg(&emb[(size_t)m * EMB + k])     : 0.0f;
    float v1 = (k + 1 < EMB) ? __ldg(&emb[(size_t)m * EMB + k + 1]) : 0.0f;
    __nv_bfloat16 h0 = __float2bfloat16(v0), h1 = __float2bfloat16(v1);
    __nv_bfloat16 l0 = __float2bfloat16(v0 - __bfloat162float(h0));
    __nv_bfloat16 l1 = __float2bfloat16(v1 - __bfloat162float(h1));
    uint32_t hp = (uint32_t)reinterpret_cast<unsigned short&>(h0) |
                  ((uint32_t)reinterpret_cast<unsigned short&>(h1) << 16);
    uint32_t lp = (uint32_t)reinterpret_cast<unsigned short&>(l0) |
                  ((uint32_t)reinterpret_cast<unsigned short&>(l1) << 16);
    uint32_t* A = (uint32_t*)g_A2;
    size_t base = (size_t)m * 480;
    A[base + k2]       = hp;
    A[base + 160 + k2] = hp;
    A[base + 320 + k2] = lp;
}

// ---------------- build B2 = [Bhi | Blo | Bhi] bf16 row-major [n][960] ----------------
__global__ void convB_kernel(const float* __restrict__ w3, const float* __restrict__ w4,
                             const float* __restrict__ w5) {
    int idx = blockIdx.x * blockDim.x + threadIdx.x;
    if (idx >= NPAD * 160) return;
    int n  = idx / 160;
    int k2 = idx % 160;
    int k0 = k2 * 2;
    float v0 = 0.0f, v1 = 0.0f;
    if (n < NCOL) {
        int c = n;
#pragma unroll
        for (int q = 0; q < 2; q++) {
            int k = k0 + q;
            float v = 0.0f;
            if (k < EMB) {
                if (c < 300)      { int fk = c / 100;        int nf = c % 100;        v = __ldg(&w3[((size_t)nf * EMB + k) * 3 + fk]); }
                else if (c < 700) { int c2 = c - 300; int fk = c2 / 100; int nf = c2 % 100; v = __ldg(&w4[((size_t)nf * EMB + k) * 4 + fk]); }
                else              { int c2 = c - 700; int fk = c2 / 100; int nf = c2 % 100; v = __ldg(&w5[((size_t)nf * EMB + k) * 5 + fk]); }
            }
            if (q == 0) v0 = v; else v1 = v;
        }
    }
    __nv_bfloat16 h0 = __float2bfloat16(v0), h1 = __float2bfloat16(v1);
    __nv_bfloat16 l0 = __float2bfloat16(v0 - __bfloat162float(h0));
    __nv_bfloat16 l1 = __float2bfloat16(v1 - __bfloat162float(h1));
    uint32_t hp = (uint32_t)reinterpret_cast<unsigned short&>(h0) |
                  ((uint32_t)reinterpret_cast<unsigned short&>(h1) << 16);
    uint32_t lp = (uint32_t)reinterpret_cast<unsigned short&>(l0) |
                  ((uint32_t)reinterpret_cast<unsigned short&>(l1) << 16);
    uint32_t* B = (uint32_t*)g_B2;
    size_t base = (size_t)n * 480;
    B[base + k2]       = hp;
    B[base + 160 + k2] = lp;
    B[base + 320 + k2] = hp;
}

// ---------------- HMMA GEMM: P[32000][1200] = A2 @ B2^T, 128x128 tile, BK=64 ----------------
// dyn smem: [buf0: A 16K | B 16K][buf1: A 16K | B 16K] = 64 KB
__device__ __forceinline__ void load_chunk(uint32_t sAb, uint32_t sBb, int bm, int bn,
                                           int kk, int tid) {
    const uint8_t* Ab = (const uint8_t*)g_A2;
    const uint8_t* Bb = (const uint8_t*)g_B2;
#pragma unroll
    for (int i = 0; i < 4; i++) {
        int id = tid + i * 256;
        int r = id >> 3, c = id & 7;
        uint32_t d = sAb + r * 128 + ((c ^ (r & 7)) << 4);
        CP_ASYNC16(d, Ab + (size_t)(bm + r) * (KTOT * 2) + kk * 2 + c * 16);
    }
#pragma unroll
    for (int i = 0; i < 4; i++) {
        int id = tid + i * 256;
        int r = id >> 3, c = id & 7;
        uint32_t d = sBb + r * 128 + ((c ^ (r & 7)) << 4);
        CP_ASYNC16(d, Bb + (size_t)(bn + r) * (KTOT * 2) + kk * 2 + c * 16);
    }
}

__global__ void __launch_bounds__(256) pgemm_mma_kernel() {
    extern __shared__ __align__(128) uint8_t dyn[];
    uint32_t sbase = smem_u32(dyn);
    int tid  = threadIdx.x;
    int wid  = tid >> 5, lane = tid & 31;
    int m0   = (wid & 1) * 64;
    int n0   = (wid >> 1) * 32;
    int bm   = blockIdx.y * 128;
    int bn   = blockIdx.x * 128;

    float acc[4][4][4];
#pragma unroll
    for (int i = 0; i < 4; i++)
#pragma unroll
        for (int j = 0; j < 4; j++)
#pragma unroll
            for (int q = 0; q < 4; q++) acc[i][j][q] = 0.0f;

    load_chunk(sbase, sbase + 16384, bm, bn, 0, tid);
    CP_COMMIT();

#pragma unroll 1
    for (int it = 0; it < 15; it++) {
        if (it < 14) {
            uint32_t nb = sbase + ((it + 1) & 1) * 32768;
            load_chunk(nb, nb + 16384, bm, bn, (it + 1) * 64, tid);
            CP_COMMIT();
            CP_WAIT(1);
        } else {
            CP_WAIT(0);
        }
        __syncthreads();

        uint32_t sAb = sbase + (it & 1) * 32768;
        uint32_t sBb = sAb + 16384;
#pragma unroll
        for (int ks = 0; ks < 4; ks++) {
            uint32_t a[4][4];
#pragma unroll
            for (int mf = 0; mf < 4; mf++) {
                int row = m0 + mf * 16 + (lane & 15);
                int ch  = ks * 2 + (lane >> 4);
                uint32_t addr = sAb + row * 128 + ((ch ^ (row & 7)) << 4);
                LDMX4(a[mf][0], a[mf][1], a[mf][2], a[mf][3], addr);
            }
            uint32_t b[4][2];
#pragma unroll
            for (int p = 0; p < 2; p++) {
                int sel = lane >> 3;
                int row = n0 + p * 16 + ((sel >> 1) << 3) + (lane & 7);
                int ch  = ks * 2 + (sel & 1);
                uint32_t addr = sBb + row * 128 + ((ch ^ (row & 7)) << 4);
                uint32_t r0, r1, r2, r3;
                LDMX4(r0, r1, r2, r3, addr);
                b[p * 2][0] = r0; b[p * 2][1] = r1;
                b[p * 2 + 1][0] = r2; b[p * 2 + 1][1] = r3;
            }
#pragma unroll
            for (int mf = 0; mf < 4; mf++)
#pragma unroll
                for (int nf = 0; nf < 4; nf++)
                    MMA16816(acc[mf][nf], a[mf], b[nf]);
        }
        __syncthreads();
    }

    // epilogue
#pragma unroll
    for (int mf = 0; mf < 4; mf++) {
        int row0 = bm + m0 + mf * 16 + (lane >> 2);
#pragma unroll
        for (int nf = 0; nf < 4; nf++) {
            int col = bn + n0 + nf * 8 + 2 * (lane & 3);
            if (col < NCOL) {
                *(float2*)(g_P + (size_t)row0 * NCOL + col) =
                    make_float2(acc[mf][nf][0], acc[mf][nf][1]);
                *(float2*)(g_P + (size_t)(row0 + 8) * NCOL + col) =
                    make_float2(acc[mf][nf][2], acc[mf][nf][3]);
            }
        }
    }
}

// ---------------- conv gather + max-pool + bias + relu ----------------
__global__ void conv_gather_kernel(const int* __restrict__ dia,
                                   const float* __restrict__ b3,
                                   const float* __restrict__ b4,
                                   const float* __restrict__ b5) {
    int bt = blockIdx.x;
    __shared__ int tok[LL];
    int tid = threadIdx.x;
    if (tid < LL) tok[tid] = dia[bt * LL + tid] * NCOL;
    __syncthreads();
    if (tid >= NFLT) return;
    int nf = tid;
    const float* P = g_P;

    float m3 = -1e30f;
    for (int p = 0; p < 46; p++) {
        float s = __ldg(&P[(size_t)tok[p] + nf]) +
                  __ldg(&P[(size_t)tok[p + 1] + 100 + nf]) +
                  __ldg(&P[(size_t)tok[p + 2] + 200 + nf]);
        m3 = fmaxf(m3, s);
    }
    g_rin[bt * 300 + nf] = fmaxf(m3 + b3[nf], 0.0f);

    float m4 = -1e30f;
    for (int p = 0; p < 45; p++) {
        float s = __ldg(&P[(size_t)tok[p] + 300 + nf]) +
                  __ldg(&P[(size_t)tok[p + 1] + 400 + nf]) +
                  __ldg(&P[(size_t)tok[p + 2] + 500 + nf]) +
                  __ldg(&P[(size_t)tok[p + 3] + 600 + nf]);
        m4 = fmaxf(m4, s);
    }
    g_rin[bt * 300 + 100 + nf] = fmaxf(m4 + b4[nf], 0.0f);

    float m5 = -1e30f;
    for (int p = 0; p < 44; p++) {
        float s = __ldg(&P[(size_t)tok[p] + 700 + nf]) +
                  __ldg(&P[(size_t)tok[p + 1] + 800 + nf]) +
                  __ldg(&P[(size_t)tok[p + 2] + 900 + nf]) +
                  __ldg(&P[(size_t)tok[p + 3] + 1000 + nf]) +
                  __ldg(&P[(size_t)tok[p + 4] + 1100 + nf]);
        m5 = fmaxf(m5, s);
    }
    g_rin[bt * 300 + 200 + nf] = fmaxf(m5 + b5[nf], 0.0f);
}

// ---------------- xg GEMM ----------------
__global__ void xg_gemm_kernel(const float* __restrict__ wih_f, const float* __restrict__ wih_r,
                               const float* __restrict__ bih_f, const float* __restrict__ bhh_f,
                               const float* __restrict__ bih_r, const float* __restrict__ bhh_r) {
    const int K = 300;
    __shared__ float sA[16][132];
    __shared__ float sB[16][68];
    int dir = blockIdx.z;
    const float* W  = dir ? wih_r : wih_f;
    const float* bi = dir ? bih_r : bih_f;
    const float* bh = dir ? bhh_r : bhh_f;
    int bm = blockIdx.y * 128;
    int bn = blockIdx.x * 64;
    int tid = threadIdx.x;
    int tx = tid & 15, ty = tid >> 4;
    float acc[8][4] = {};
    for (int kk = 0; kk < K; kk += 16) {
        int ak = tid & 15, am = tid >> 4;
        int gk = kk + ak;
#pragma unroll
        for (int i = 0; i < 8; i++) {
            int m  = am + i * 16;
            int gm = bm + m;
            int t  = gm >> 5, bb = gm & 31;
            int st = dir ? (63 - t) : t;
            sA[ak][m] = (gk < K) ? __ldg(&g_rin[(bb * 64 + st) * 300 + gk]) : 0.0f;
        }
        int wk = tid & 15, wn = tid >> 4;
#pragma unroll
        for (int i = 0; i < 4; i++) {
            int n   = wn + i * 16;
            int gkb = kk + wk;
            sB[wk][n] = (gkb < K) ? __ldg(&W[(bn + n) * 300 + gkb]) : 0.0f;
        }
        __syncthreads();
#pragma unroll
        for (int k = 0; k < 16; k++) {
            float4 a0 = *(const float4*)&sA[k][ty * 8];
            float4 a1 = *(const float4*)&sA[k][ty * 8 + 4];
            float4 b0 = *(const float4*)&sB[k][tx * 4];
            float ra[8] = {a0.x, a0.y, a0.z, a0.w, a1.x, a1.y, a1.z, a1.w};
            float rb[4] = {b0.x, b0.y, b0.z, b0.w};
#pragma unroll
            for (int i = 0; i < 8; i++)
#pragma unroll
                for (int j = 0; j < 4; j++) acc[i][j] += ra[i] * rb[j];
        }
        __syncthreads();
    }
#pragma unroll
    for (int i = 0; i < 8; i++) {
        int gm = bm + ty * 8 + i;
        int t = gm >> 5, bb = gm & 31;
#pragma unroll
        for (int j = 0; j < 4; j++) {
            int g = bn + tx * 4 + j;
            g_XG[(((size_t)dir * 64 + t) * 1024 + g) * 32 + bb] =
                acc[i][j] + __ldg(&bi[g]) + __ldg(&bh[g]);
        }
    }
}

// ---------------- persistent BiLSTM ----------------
__global__ void lstm_kernel(const float* __restrict__ whh_f, const float* __restrict__ whh_r) {
    extern __shared__ float sm[];
    float* sW = sm;
    float* sH = sm + 8192;
    int cta = blockIdx.x;
    int dir = cta >> 5;
    int j0  = (cta & 31) * 8;
    int tid = threadIdx.x;
    int jj  = tid >> 5;
    int b   = tid & 31;
    const float* whh = dir ? whh_r : whh_f;

    for (int i = tid; i < 8192; i += 256) {
        int k = i & 255;
        int r = i >> 8;
        int gate = r & 3, jjj = r >> 2;
        sW[(jjj * 4 + gate) * 256 + k] = __ldg(&whh[(gate * 256 + j0 + jjj) * 256 + k]);
    }

    int j = j0 + jj;
    const float4* w0 = (const float4*)(sW + (jj * 4 + 0) * 256);
    const float4* w1 = (const float4*)(sW + (jj * 4 + 1) * 256);
    const float4* w2 = (const float4*)(sW + (jj * 4 + 2) * 256);
    const float4* w3 = (const float4*)(sW + (jj * 4 + 3) * 256);
    float c = 0.0f;
    __syncthreads();

    for (int s = 0; s < 64; s++) {
        int rb = s & 1;
        const float* hprev = g_Hbuf + (rb * 2 + dir) * (HID * BB);
        for (int i = tid; i < HID * BB; i += 256) {
            int jx = i >> 5, bx = i & 31;
            sH[bx * 260 + jx] = __ldcg(&hprev[i]);
        }
        __syncthreads();

        size_t xbase = (((size_t)dir * 64 + s) * 1024) * 32;
        float ai = __ldg(&g_XG[xbase + (size_t)(0   + j) * 32 + b]);
        float af = __ldg(&g_XG[xbase + (size_t)(256 + j) * 32 + b]);
        float ag = __ldg(&g_XG[xbase + (size_t)(512 + j) * 32 + b]);
        float ao = __ldg(&g_XG[xbase + (size_t)(768 + j) * 32 + b]);

        const float4* h4 = (const float4*)(sH + b * 260);
#pragma unroll 8
        for (int k = 0; k < 64; k++) {
            float4 h = h4[k];
            float4 x;
            x = w0[k]; ai += h.x * x.x + h.y * x.y + h.z * x.z + h.w * x.w;
            x = w1[k]; af += h.x * x.x + h.y * x.y + h.z * x.z + h.w * x.w;
            x = w2[k]; ag += h.x * x.x + h.y * x.y + h.z * x.z + h.w * x.w;
            x = w3[k]; ao += h.x * x.x + h.y * x.y + h.z * x.z + h.w * x.w;
        }

        float iv = sigf(ai), fv = sigf(af), gv = tanhf(ag), ov = sigf(ao);
        c = fv * c + iv * gv;
        float h = ov * tanhf(c);

        int wb = rb ^ 1;
        __stcg(&g_Hbuf[(wb * 2 + dir) * (HID * BB) + j * 32 + b], h);
        int tout = dir ? (63 - s) : s;
        g_HS[(((size_t)dir * 64 + tout) * HID + j) * 32 + b] = h;

        __threadfence();
        __syncthreads();
        if (tid == 0) {
            atomicAdd(&g_bar[s], 1);
            volatile int* bp = (volatile int*)&g_bar[s];
            while (*bp < 64) { __nanosleep(32); }
        }
        __syncthreads();
    }
}

// ---------------- head ----------------
__global__ void head_kernel(const float* __restrict__ hw, const float* __restrict__ hb,
                            float* __restrict__ out) {
    int t = blockIdx.x;
    int tid = threadIdx.x;
    int b  = tid & 31;
    int og = tid >> 5;
    const float* hf = g_HS + (size_t)(t * HID) * 32;
    const float* hr = g_HS + (size_t)((64 + t) * HID) * 32;
    float a0 = 0.f, a1 = 0.f, a2 = 0.f, a3 = 0.f;
    int o = og * 4;
    for (int h = 0; h < HID; h++) {
        float vf = __ldg(&hf[h * 32 + b]);
        float vr = __ldg(&hr[h * 32 + b]);
        a0 += vf * __ldg(&hw[(o + 0) * 512 + h]) + vr * __ldg(&hw[(o + 0) * 512 + 256 + h]);
        a1 += vf * __ldg(&hw[(o + 1) * 512 + h]) + vr * __ldg(&hw[(o + 1) * 512 + 256 + h]);
        a2 += vf * __ldg(&hw[(o + 2) * 512 + h]) + vr * __ldg(&hw[(o + 2) * 512 + 256 + h]);
        a3 += vf * __ldg(&hw[(o + 3) * 512 + h]) + vr * __ldg(&hw[(o + 3) * 512 + 256 + h]);
    }
    size_t base = ((size_t)b * 64 + t) * 32 + o;
    out[base + 0] = sigf(a0 + __ldg(&hb[o + 0]));
    out[base + 1] = sigf(a1 + __ldg(&hb[o + 1]));
    out[base + 2] = sigf(a2 + __ldg(&hb[o + 2]));
    out[base + 3] = sigf(a3 + __ldg(&hb[o + 3]));
}

// ---------------- launch ----------------
extern "C" void kernel_launch(void* const* d_in, const int* in_sizes, int n_in,
                              void* d_out, int out_size) {
    const int*   dialogue = (const int*)d_in[0];
    const float* emb   = (const float*)d_in[1];
    const float* w3    = (const float*)d_in[2];
    const float* b3    = (const float*)d_in[3];
    const float* w4    = (const float*)d_in[4];
    const float* b4    = (const float*)d_in[5];
    const float* w5    = (const float*)d_in[6];
    const float* b5    = (const float*)d_in[7];
    const float* wih_f = (const float*)d_in[8];
    const float* whh_f = (const float*)d_in[9];
    const float* bih_f = (const float*)d_in[10];
    const float* bhh_f = (const float*)d_in[11];
    const float* wih_r = (const float*)d_in[12];
    const float* whh_r = (const float*)d_in[13];
    const float* bih_r = (const float*)d_in[14];
    const float* bhh_r = (const float*)d_in[15];
    const float* hw    = (const float*)d_in[16];
    const float* hb    = (const float*)d_in[17];
    float* out = (float*)d_out;

    cudaFuncSetAttribute(pgemm_mma_kernel, cudaFuncAttributeMaxDynamicSharedMemorySize, 65536);
    cudaFuncSetAttribute(lstm_kernel, cudaFuncAttributeMaxDynamicSharedMemorySize,
                         (8192 + 32 * 260) * (int)sizeof(float));

    init_kernel<<<64, 256>>>();
    convA_kernel<<<(VOCAB * 160 + 255) / 256, 256>>>(emb);
    convB_kernel<<<(NPAD * 160 + 255) / 256, 256>>>(w3, w4, w5);

    dim3 gP(NTILES, MTILES);
    pgemm_mma_kernel<<<gP, 256, 65536>>>();

    conv_gather_kernel<<<BT, 128>>>(dialogue, b3, b4, b5);

    dim3 gX(16, 16, 2);
    xg_gemm_kernel<<<gX, 256>>>(wih_f, wih_r, bih_f, bhh_f, bih_r, bhh_r);

    lstm_kernel<<<64, 256, (8192 + 32 * 260) * sizeof(float)>>>(whh_f, whh_r);

    head_kernel<<<TT, 256>>>(hw, hb, out);
}

// round 4
// speedup vs baseline: 1.5889x; 1.1164x over previous
#include <cuda_runtime.h>
#include <cuda_bf16.h>
#include <math.h>
#include <stdint.h>

#define VOCAB 32000
#define EMB   300
#define NFLT  100
#define HID   256
#define BB    32
#define TT    64
#define LL    48
#define NCOL  1200
#define BT    (BB*TT)

#define KTOT  960
#define NPAD  1280
#define MTILES 250
#define NTILES 10

// ---------------- device scratch ----------------
__device__ __align__(16) float g_P[(size_t)VOCAB * NCOL];
__device__ __align__(16) __nv_bfloat16 g_A2[(size_t)VOCAB * KTOT];
__device__ __align__(16) __nv_bfloat16 g_B2[(size_t)NPAD * KTOT];
__device__ float g_rin[BT * 300];
__device__ float g_XG[2 * TT * 1024 * BB];
__device__ float g_HS[2 * TT * HID * BB];
__device__ float g_Hbuf[2 * 2 * HID * BB];
__device__ int   g_bar[TT];

__device__ __forceinline__ float sigf(float x) { return 1.0f / (1.0f + expf(-x)); }

__device__ __forceinline__ uint32_t smem_u32(const void* p) {
    uint32_t a;
    asm("{ .reg .u64 t; cvta.to.shared.u64 t, %1; cvt.u32.u64 %0, t; }" : "=r"(a) : "l"(p));
    return a;
}
#define CP_ASYNC16(d, s) asm volatile("cp.async.cg.shared.global [%0], [%1], 16;" :: "r"(d), "l"(s))
#define CP_COMMIT()      asm volatile("cp.async.commit_group;" ::: "memory")
#define CP_WAIT(n)       asm volatile("cp.async.wait_group %0;" :: "n"(n) : "memory")
#define LDMX4(r0, r1, r2, r3, addr) \
    asm volatile("ldmatrix.sync.aligned.m8n8.x4.shared.b16 {%0,%1,%2,%3}, [%4];" \
                 : "=r"(r0), "=r"(r1), "=r"(r2), "=r"(r3) : "r"(addr))
#define MMA16816(c, a, b) \
    asm volatile("mma.sync.aligned.m16n8k16.row.col.f32.bf16.bf16.f32 " \
                 "{%0,%1,%2,%3}, {%4,%5,%6,%7}, {%8,%9}, {%0,%1,%2,%3};" \
                 : "+f"((c)[0]), "+f"((c)[1]), "+f"((c)[2]), "+f"((c)[3]) \
                 : "r"((a)[0]), "r"((a)[1]), "r"((a)[2]), "r"((a)[3]), "r"((b)[0]), "r"((b)[1]))

// ---------------- init ----------------
__global__ void init_kernel() {
    int idx = blockIdx.x * blockDim.x + threadIdx.x;
    int n = 2 * 2 * HID * BB;
    for (int i = idx; i < n; i += gridDim.x * blockDim.x) g_Hbuf[i] = 0.0f;
    if (idx < TT) g_bar[idx] = 0;
}

// ---------------- build A2 = [Ahi | Ahi | Alo] ----------------
__global__ void convA_kernel(const float* __restrict__ emb) {
    int idx = blockIdx.x * blockDim.x + threadIdx.x;
    if (idx >= VOCAB * 160) return;
    int m  = idx / 160;
    int k2 = idx % 160;
    int k  = k2 * 2;
    float v0 = (k     < EMB) ? __ldg(&emb[(size_t)m * EMB + k])     : 0.0f;
    float v1 = (k + 1 < EMB) ? __ldg(&emb[(size_t)m * EMB + k + 1]) : 0.0f;
    __nv_bfloat16 h0 = __float2bfloat16(v0), h1 = __float2bfloat16(v1);
    __nv_bfloat16 l0 = __float2bfloat16(v0 - __bfloat162float(h0));
    __nv_bfloat16 l1 = __float2bfloat16(v1 - __bfloat162float(h1));
    uint32_t hp = (uint32_t)reinterpret_cast<unsigned short&>(h0) |
                  ((uint32_t)reinterpret_cast<unsigned short&>(h1) << 16);
    uint32_t lp = (uint32_t)reinterpret_cast<unsigned short&>(l0) |
                  ((uint32_t)reinterpret_cast<unsigned short&>(l1) << 16);
    uint32_t* A = (uint32_t*)g_A2;
    size_t base = (size_t)m * 480;
    A[base + k2]       = hp;
    A[base + 160 + k2] = hp;
    A[base + 320 + k2] = lp;
}

// ---------------- build B2 = [Bhi | Blo | Bhi] ----------------
__global__ void convB_kernel(const float* __restrict__ w3, const float* __restrict__ w4,
                             const float* __restrict__ w5) {
    int idx = blockIdx.x * blockDim.x + threadIdx.x;
    if (idx >= NPAD * 160) return;
    int n  = idx / 160;
    int k2 = idx % 160;
    int k0 = k2 * 2;
    float v0 = 0.0f, v1 = 0.0f;
    if (n < NCOL) {
        int c = n;
#pragma unroll
        for (int q = 0; q < 2; q++) {
            int k = k0 + q;
            float v = 0.0f;
            if (k < EMB) {
                if (c < 300)      { int fk = c / 100;        int nf = c % 100;        v = __ldg(&w3[((size_t)nf * EMB + k) * 3 + fk]); }
                else if (c < 700) { int c2 = c - 300; int fk = c2 / 100; int nf = c2 % 100; v = __ldg(&w4[((size_t)nf * EMB + k) * 4 + fk]); }
                else              { int c2 = c - 700; int fk = c2 / 100; int nf = c2 % 100; v = __ldg(&w5[((size_t)nf * EMB + k) * 5 + fk]); }
            }
            if (q == 0) v0 = v; else v1 = v;
        }
    }
    __nv_bfloat16 h0 = __float2bfloat16(v0), h1 = __float2bfloat16(v1);
    __nv_bfloat16 l0 = __float2bfloat16(v0 - __bfloat162float(h0));
    __nv_bfloat16 l1 = __float2bfloat16(v1 - __bfloat162float(h1));
    uint32_t hp = (uint32_t)reinterpret_cast<unsigned short&>(h0) |
                  ((uint32_t)reinterpret_cast<unsigned short&>(h1) << 16);
    uint32_t lp = (uint32_t)reinterpret_cast<unsigned short&>(l0) |
                  ((uint32_t)reinterpret_cast<unsigned short&>(l1) << 16);
    uint32_t* B = (uint32_t*)g_B2;
    size_t base = (size_t)n * 480;
    B[base + k2]       = hp;
    B[base + 160 + k2] = lp;
    B[base + 320 + k2] = hp;
}

// ---------------- HMMA GEMM ----------------
__device__ __forceinline__ void load_chunk(uint32_t sAb, uint32_t sBb, int bm, int bn,
                                           int kk, int tid) {
    const uint8_t* Ab = (const uint8_t*)g_A2;
    const uint8_t* Bb = (const uint8_t*)g_B2;
#pragma unroll
    for (int i = 0; i < 4; i++) {
        int id = tid + i * 256;
        int r = id >> 3, c = id & 7;
        uint32_t d = sAb + r * 128 + ((c ^ (r & 7)) << 4);
        CP_ASYNC16(d, Ab + (size_t)(bm + r) * (KTOT * 2) + kk * 2 + c * 16);
    }
#pragma unroll
    for (int i = 0; i < 4; i++) {
        int id = tid + i * 256;
        int r = id >> 3, c = id & 7;
        uint32_t d = sBb + r * 128 + ((c ^ (r & 7)) << 4);
        CP_ASYNC16(d, Bb + (size_t)(bn + r) * (KTOT * 2) + kk * 2 + c * 16);
    }
}

__global__ void __launch_bounds__(256, 2) pgemm_mma_kernel() {
    extern __shared__ __align__(128) uint8_t dyn[];
    uint32_t sbase = smem_u32(dyn);
    int tid  = threadIdx.x;
    int wid  = tid >> 5, lane = tid & 31;
    int m0   = (wid & 1) * 64;
    int n0   = (wid >> 1) * 32;
    int bm   = blockIdx.y * 128;
    int bn   = blockIdx.x * 128;

    float acc[4][4][4];
#pragma unroll
    for (int i = 0; i < 4; i++)
#pragma unroll
        for (int j = 0; j < 4; j++)
#pragma unroll
            for (int q = 0; q < 4; q++) acc[i][j][q] = 0.0f;

    load_chunk(sbase, sbase + 16384, bm, bn, 0, tid);
    CP_COMMIT();

#pragma unroll 1
    for (int it = 0; it < 15; it++) {
        if (it < 14) {
            uint32_t nb = sbase + ((it + 1) & 1) * 32768;
            load_chunk(nb, nb + 16384, bm, bn, (it + 1) * 64, tid);
            CP_COMMIT();
            CP_WAIT(1);
        } else {
            CP_WAIT(0);
        }
        __syncthreads();

        uint32_t sAb = sbase + (it & 1) * 32768;
        uint32_t sBb = sAb + 16384;
#pragma unroll
        for (int ks = 0; ks < 4; ks++) {
            uint32_t a[4][4];
#pragma unroll
            for (int mf = 0; mf < 4; mf++) {
                int row = m0 + mf * 16 + (lane & 15);
                int ch  = ks * 2 + (lane >> 4);
                uint32_t addr = sAb + row * 128 + ((ch ^ (row & 7)) << 4);
                LDMX4(a[mf][0], a[mf][1], a[mf][2], a[mf][3], addr);
            }
            uint32_t b[4][2];
#pragma unroll
            for (int p = 0; p < 2; p++) {
                int sel = lane >> 3;
                int row = n0 + p * 16 + ((sel >> 1) << 3) + (lane & 7);
                int ch  = ks * 2 + (sel & 1);
                uint32_t addr = sBb + row * 128 + ((ch ^ (row & 7)) << 4);
                uint32_t r0, r1, r2, r3;
                LDMX4(r0, r1, r2, r3, addr);
                b[p * 2][0] = r0; b[p * 2][1] = r1;
                b[p * 2 + 1][0] = r2; b[p * 2 + 1][1] = r3;
            }
#pragma unroll
            for (int mf = 0; mf < 4; mf++)
#pragma unroll
                for (int nf = 0; nf < 4; nf++)
                    MMA16816(acc[mf][nf], a[mf], b[nf]);
        }
        __syncthreads();
    }

#pragma unroll
    for (int mf = 0; mf < 4; mf++) {
        int row0 = bm + m0 + mf * 16 + (lane >> 2);
#pragma unroll
        for (int nf = 0; nf < 4; nf++) {
            int col = bn + n0 + nf * 8 + 2 * (lane & 3);
            if (col < NCOL) {
                *(float2*)(g_P + (size_t)row0 * NCOL + col) =
                    make_float2(acc[mf][nf][0], acc[mf][nf][1]);
                *(float2*)(g_P + (size_t)(row0 + 8) * NCOL + col) =
                    make_float2(acc[mf][nf][2], acc[mf][nf][3]);
            }
        }
    }
}

// ---------------- conv gather + max-pool + bias + relu ----------------
__global__ void conv_gather_kernel(const int* __restrict__ dia,
                                   const float* __restrict__ b3,
                                   const float* __restrict__ b4,
                                   const float* __restrict__ b5) {
    int bt = blockIdx.x;
    __shared__ int tok[LL];
    int tid = threadIdx.x;
    if (tid < LL) tok[tid] = dia[bt * LL + tid] * NCOL;
    __syncthreads();
    if (tid >= NFLT) return;
    int nf = tid;
    const float* P = g_P;

    float m3 = -1e30f;
    for (int p = 0; p < 46; p++) {
        float s = __ldg(&P[(size_t)tok[p] + nf]) +
                  __ldg(&P[(size_t)tok[p + 1] + 100 + nf]) +
                  __ldg(&P[(size_t)tok[p + 2] + 200 + nf]);
        m3 = fmaxf(m3, s);
    }
    g_rin[bt * 300 + nf] = fmaxf(m3 + b3[nf], 0.0f);

    float m4 = -1e30f;
    for (int p = 0; p < 45; p++) {
        float s = __ldg(&P[(size_t)tok[p] + 300 + nf]) +
                  __ldg(&P[(size_t)tok[p + 1] + 400 + nf]) +
                  __ldg(&P[(size_t)tok[p + 2] + 500 + nf]) +
                  __ldg(&P[(size_t)tok[p + 3] + 600 + nf]);
        m4 = fmaxf(m4, s);
    }
    g_rin[bt * 300 + 100 + nf] = fmaxf(m4 + b4[nf], 0.0f);

    float m5 = -1e30f;
    for (int p = 0; p < 44; p++) {
        float s = __ldg(&P[(size_t)tok[p] + 700 + nf]) +
                  __ldg(&P[(size_t)tok[p + 1] + 800 + nf]) +
                  __ldg(&P[(size_t)tok[p + 2] + 900 + nf]) +
                  __ldg(&P[(size_t)tok[p + 3] + 1000 + nf]) +
                  __ldg(&P[(size_t)tok[p + 4] + 1100 + nf]);
        m5 = fmaxf(m5, s);
    }
    g_rin[bt * 300 + 200 + nf] = fmaxf(m5 + b5[nf], 0.0f);
}

// ---------------- xg GEMM ----------------
__global__ void xg_gemm_kernel(const float* __restrict__ wih_f, const float* __restrict__ wih_r,
                               const float* __restrict__ bih_f, const float* __restrict__ bhh_f,
                               const float* __restrict__ bih_r, const float* __restrict__ bhh_r) {
    const int K = 300;
    __shared__ float sA[16][132];
    __shared__ float sB[16][68];
    int dir = blockIdx.z;
    const float* W  = dir ? wih_r : wih_f;
    const float* bi = dir ? bih_r : bih_f;
    const float* bh = dir ? bhh_r : bhh_f;
    int bm = blockIdx.y * 128;
    int bn = blockIdx.x * 64;
    int tid = threadIdx.x;
    int tx = tid & 15, ty = tid >> 4;
    float acc[8][4] = {};
    for (int kk = 0; kk < K; kk += 16) {
        int ak = tid & 15, am = tid >> 4;
        int gk = kk + ak;
#pragma unroll
        for (int i = 0; i < 8; i++) {
            int m  = am + i * 16;
            int gm = bm + m;
            int t  = gm >> 5, bb = gm & 31;
            int st = dir ? (63 - t) : t;
            sA[ak][m] = (gk < K) ? __ldg(&g_rin[(bb * 64 + st) * 300 + gk]) : 0.0f;
        }
        int wk = tid & 15, wn = tid >> 4;
#pragma unroll
        for (int i = 0; i < 4; i++) {
            int n   = wn + i * 16;
            int gkb = kk + wk;
            sB[wk][n] = (gkb < K) ? __ldg(&W[(bn + n) * 300 + gkb]) : 0.0f;
        }
        __syncthreads();
#pragma unroll
        for (int k = 0; k < 16; k++) {
            float4 a0 = *(const float4*)&sA[k][ty * 8];
            float4 a1 = *(const float4*)&sA[k][ty * 8 + 4];
            float4 b0 = *(const float4*)&sB[k][tx * 4];
            float ra[8] = {a0.x, a0.y, a0.z, a0.w, a1.x, a1.y, a1.z, a1.w};
            float rb[4] = {b0.x, b0.y, b0.z, b0.w};
#pragma unroll
            for (int i = 0; i < 8; i++)
#pragma unroll
                for (int j = 0; j < 4; j++) acc[i][j] += ra[i] * rb[j];
        }
        __syncthreads();
    }
#pragma unroll
    for (int i = 0; i < 8; i++) {
        int gm = bm + ty * 8 + i;
        int t = gm >> 5, bb = gm & 31;
#pragma unroll
        for (int j = 0; j < 4; j++) {
            int g = bn + tx * 4 + j;
            g_XG[(((size_t)dir * 64 + t) * 1024 + g) * 32 + bb] =
                acc[i][j] + __ldg(&bi[g]) + __ldg(&bh[g]);
        }
    }
}

// ---------------- persistent BiLSTM v2: 128 CTAs (2 dir x 64 j-slices of 4) ----------------
// 256 threads: b = tid&31, kh = (tid>>5)&1, jj = tid>>6
// smem: sW[4jj][4g][256] 16KB | sH[2kh][32b][132] 33.8KB | sPart[4jj][4g][32b] 8KB
#define LS_W    0
#define LS_H    4096
#define LS_PART (4096 + 8448)
#define LS_TOT  (4096 + 8448 + 2048)

__global__ void lstm_kernel(const float* __restrict__ whh_f, const float* __restrict__ whh_r) {
    extern __shared__ float sm[];
    float* sW = sm + LS_W;
    float* sH = sm + LS_H;
    float* sP = sm + LS_PART;
    int cta = blockIdx.x;
    int dir = cta >> 6;
    int j0  = (cta & 63) * 4;
    int tid = threadIdx.x;
    int b   = tid & 31;
    int kh  = (tid >> 5) & 1;
    int jj  = tid >> 6;
    const float* whh = dir ? whh_r : whh_f;

    // load weights: sW[jj][g][k]
    for (int i = tid; i < 4096; i += 256) {
        int k = i & 255;
        int g = (i >> 8) & 3;
        int jx = i >> 10;
        sW[(jx * 4 + g) * 256 + k] = __ldg(&whh[(g * 256 + j0 + jx) * 256 + k]);
    }

    int j = j0 + jj;
    const float4* w0 = (const float4*)(sW + (jj * 4 + 0) * 256 + kh * 128);
    const float4* w1 = (const float4*)(sW + (jj * 4 + 1) * 256 + kh * 128);
    const float4* w2 = (const float4*)(sW + (jj * 4 + 2) * 256 + kh * 128);
    const float4* w3 = (const float4*)(sW + (jj * 4 + 3) * 256 + kh * 128);
    float c = 0.0f;
    __syncthreads();

    for (int s = 0; s < 64; s++) {
        int rb = s & 1;
        const float* hprev = g_Hbuf + (rb * 2 + dir) * (HID * BB);
        // fill sH[kh'][b'][k'] where k = index>>5 (0..255), b' = index&31
        for (int i = tid; i < HID * BB; i += 256) {
            int jxx = i >> 5, bx = i & 31;
            sH[((jxx >> 7) * 32 + bx) * 132 + (jxx & 127)] = __ldcg(&hprev[i]);
        }
        __syncthreads();

        float ai = 0.f, af = 0.f, ag = 0.f, ao = 0.f;
        const float4* h4 = (const float4*)(sH + (kh * 32 + b) * 132);
#pragma unroll 4
        for (int k = 0; k < 32; k++) {
            float4 h = h4[k];
            float4 x;
            x = w0[k]; ai += h.x * x.x + h.y * x.y + h.z * x.z + h.w * x.w;
            x = w1[k]; af += h.x * x.x + h.y * x.y + h.z * x.z + h.w * x.w;
            x = w2[k]; ag += h.x * x.x + h.y * x.y + h.z * x.z + h.w * x.w;
            x = w3[k]; ao += h.x * x.x + h.y * x.y + h.z * x.z + h.w * x.w;
        }

        if (kh == 1) {
            sP[(jj * 4 + 0) * 32 + b] = ai;
            sP[(jj * 4 + 1) * 32 + b] = af;
            sP[(jj * 4 + 2) * 32 + b] = ag;
            sP[(jj * 4 + 3) * 32 + b] = ao;
        }
        __syncthreads();

        if (kh == 0) {
            size_t xbase = (((size_t)dir * 64 + s) * 1024) * 32;
            ai += sP[(jj * 4 + 0) * 32 + b] + __ldg(&g_XG[xbase + (size_t)(0   + j) * 32 + b]);
            af += sP[(jj * 4 + 1) * 32 + b] + __ldg(&g_XG[xbase + (size_t)(256 + j) * 32 + b]);
            ag += sP[(jj * 4 + 2) * 32 + b] + __ldg(&g_XG[xbase + (size_t)(512 + j) * 32 + b]);
            ao += sP[(jj * 4 + 3) * 32 + b] + __ldg(&g_XG[xbase + (size_t)(768 + j) * 32 + b]);

            float iv = sigf(ai), fv = sigf(af), gv = tanhf(ag), ov = sigf(ao);
            c = fv * c + iv * gv;
            float h = ov * tanhf(c);

            int wb = rb ^ 1;
            __stcg(&g_Hbuf[(wb * 2 + dir) * (HID * BB) + j * 32 + b], h);
            int tout = dir ? (63 - s) : s;
            g_HS[(((size_t)dir * 64 + tout) * HID + j) * 32 + b] = h;
        }

        __threadfence();
        __syncthreads();
        if (tid == 0) {
            atomicAdd(&g_bar[s], 1);
            volatile int* bp = (volatile int*)&g_bar[s];
            while (*bp < 128) { __nanosleep(32); }
        }
        __syncthreads();
    }
}

// ---------------- head ----------------
__global__ void head_kernel(const float* __restrict__ hw, const float* __restrict__ hb,
                            float* __restrict__ out) {
    int t = blockIdx.x;
    int tid = threadIdx.x;
    int b  = tid & 31;
    int og = tid >> 5;
    const float* hf = g_HS + (size_t)(t * HID) * 32;
    const float* hr = g_HS + (size_t)((64 + t) * HID) * 32;
    float a0 = 0.f, a1 = 0.f, a2 = 0.f, a3 = 0.f;
    int o = og * 4;
    for (int h = 0; h < HID; h++) {
        float vf = __ldg(&hf[h * 32 + b]);
        float vr = __ldg(&hr[h * 32 + b]);
        a0 += vf * __ldg(&hw[(o + 0) * 512 + h]) + vr * __ldg(&hw[(o + 0) * 512 + 256 + h]);
        a1 += vf * __ldg(&hw[(o + 1) * 512 + h]) + vr * __ldg(&hw[(o + 1) * 512 + 256 + h]);
        a2 += vf * __ldg(&hw[(o + 2) * 512 + h]) + vr * __ldg(&hw[(o + 2) * 512 + 256 + h]);
        a3 += vf * __ldg(&hw[(o + 3) * 512 + h]) + vr * __ldg(&hw[(o + 3) * 512 + 256 + h]);
    }
    size_t base = ((size_t)b * 64 + t) * 32 + o;
    out[base + 0] = sigf(a0 + __ldg(&hb[o + 0]));
    out[base + 1] = sigf(a1 + __ldg(&hb[o + 1]));
    out[base + 2] = sigf(a2 + __ldg(&hb[o + 2]));
    out[base + 3] = sigf(a3 + __ldg(&hb[o + 3]));
}

// ---------------- launch ----------------
extern "C" void kernel_launch(void* const* d_in, const int* in_sizes, int n_in,
                              void* d_out, int out_size) {
    const int*   dialogue = (const int*)d_in[0];
    const float* emb   = (const float*)d_in[1];
    const float* w3    = (const float*)d_in[2];
    const float* b3    = (const float*)d_in[3];
    const float* w4    = (const float*)d_in[4];
    const float* b4    = (const float*)d_in[5];
    const float* w5    = (const float*)d_in[6];
    const float* b5    = (const float*)d_in[7];
    const float* wih_f = (const float*)d_in[8];
    const float* whh_f = (const float*)d_in[9];
    const float* bih_f = (const float*)d_in[10];
    const float* bhh_f = (const float*)d_in[11];
    const float* wih_r = (const float*)d_in[12];
    const float* whh_r = (const float*)d_in[13];
    const float* bih_r = (const float*)d_in[14];
    const float* bhh_r = (const float*)d_in[15];
    const float* hw    = (const float*)d_in[16];
    const float* hb    = (const float*)d_in[17];
    float* out = (float*)d_out;

    cudaFuncSetAttribute(pgemm_mma_kernel, cudaFuncAttributeMaxDynamicSharedMemorySize, 65536);
    cudaFuncSetAttribute(lstm_kernel, cudaFuncAttributeMaxDynamicSharedMemorySize,
                         LS_TOT * (int)sizeof(float));

    init_kernel<<<64, 256>>>();
    convA_kernel<<<(VOCAB * 160 + 255) / 256, 256>>>(emb);
    convB_kernel<<<(NPAD * 160 + 255) / 256, 256>>>(w3, w4, w5);

    dim3 gP(NTILES, MTILES);
    pgemm_mma_kernel<<<gP, 256, 65536>>>();

    conv_gather_kernel<<<BT, 128>>>(dialogue, b3, b4, b5);

    dim3 gX(16, 16, 2);
    xg_gemm_kernel<<<gX, 256>>>(wih_f, wih_r, bih_f, bhh_f, bih_r, bhh_r);

    lstm_kernel<<<128, 256, LS_TOT * sizeof(float)>>>(whh_f, whh_r);

    head_kernel<<<TT, 256>>>(hw, hb, out);
}